// round 14
// baseline (speedup 1.0000x reference)
#include <cuda_runtime.h>
#include <math.h>
#include <cstdint>

#define NB 64
#define NS 512
#define NF 1024
#define SST 36   // gemm smem row stride in floats

static __device__ float g_P[NB * NS * NF];      // x_proj, [b][s][h]
static __device__ float g_H[NB * NS * NF];      // x_rounded, then tf32-rounded h
static __device__ float g_Wx[NF * NF];          // tf32-rounded W_x
static __device__ float g_Who[NF * NF];         // tf32-rounded W_ho
static __device__ float g_ring[2 * 1032 * 64];  // transposed h ring [slot][k][b]
static __device__ unsigned g_qctr[8][32];       // (grp*4+Q) counters, 1 line apart

typedef unsigned long long ull;

__device__ __forceinline__ ull pack2(float x) {
    ull r; asm("mov.b64 %0, {%1, %1};" : "=l"(r) : "f"(x)); return r;
}
__device__ __forceinline__ float2 unpack2(ull v) {
    float2 r; asm("mov.b64 {%0, %1}, %2;" : "=f"(r.x), "=f"(r.y) : "l"(v)); return r;
}
__device__ __forceinline__ void fma2(ull& d, ull a, ull b) {
    asm("fma.rn.f32x2 %0, %1, %2, %0;" : "+l"(d) : "l"(a), "l"(b));
}
__device__ __forceinline__ void add2(ull& d, ull a) {
    asm("add.rn.f32x2 %0, %0, %1;" : "+l"(d) : "l"(a));
}
__device__ __forceinline__ float tf32r(float x) {
    float r; asm("cvt.rna.tf32.f32 %0, %1;" : "=f"(r) : "f"(x)); return r;
}
__device__ __forceinline__ uint32_t smem_u32(const void* p) {
    uint32_t a;
    asm("{ .reg .u64 t; cvta.to.shared.u64 t, %1; cvt.u32.u64 %0, t; }" : "=r"(a) : "l"(p));
    return a;
}
__device__ __forceinline__ void cp_async16(uint32_t dst, const void* src) {
    asm volatile("cp.async.cg.shared.global [%0], [%1], 16;" :: "r"(dst), "l"(src) : "memory");
}
__device__ __forceinline__ void mma_m16n8k8(float* c, const uint32_t* a,
                                            uint32_t b0, uint32_t b1) {
    asm volatile(
        "mma.sync.aligned.m16n8k8.row.col.f32.tf32.tf32.f32 "
        "{%0,%1,%2,%3}, {%4,%5,%6,%7}, {%8,%9}, {%0,%1,%2,%3};"
        : "+f"(c[0]), "+f"(c[1]), "+f"(c[2]), "+f"(c[3])
        : "r"(a[0]), "r"(a[1]), "r"(a[2]), "r"(a[3]), "r"(b0), "r"(b1));
}

__global__ void knop() {}

// ---------------------------------------------------------------------------
// Fused init: tf32-round x -> g_H, round weights, ring slot 1 <- h0^T, ctrs.
// ---------------------------------------------------------------------------
__global__ void fused_init(const float* __restrict__ x,
                           const float* __restrict__ Wih,
                           const float* __restrict__ Who,
                           const float* __restrict__ h0)
{
    int i = blockIdx.x * 256 + threadIdx.x;   // float4 idx
    float4 v = ((const float4*)x)[i];
    v.x = tf32r(v.x); v.y = tf32r(v.y); v.z = tf32r(v.z); v.w = tf32r(v.w);
    ((float4*)g_H)[i] = v;

    if (i < NF * NF) {
        int n = i >> 10, k = i & 1023;
        g_Wx[i]  = tf32r(Wih[(size_t)n * 2048 + k]);
        g_Who[i] = tf32r(Who[i]);
    }
    if (i < 65536) {
        int k = i >> 6, b = i & 63;
        g_ring[1032 * 64 + k * 64 + b] = h0[b * 1024 + k];
    }
    if (i < 256) ((unsigned*)g_qctr)[i] = 0u;
}

// ---------------------------------------------------------------------------
// tf32 mma.sync GEMM (round-7 version, measured 603us).
// ---------------------------------------------------------------------------
__global__ void __launch_bounds__(256, 2) gemm_mma(
    const float* __restrict__ A, const float* __restrict__ B,
    const float* __restrict__ bias, float* __restrict__ C)
{
    extern __shared__ float sm[];
    const int tid = threadIdx.x;
    const int wid = tid >> 5, lane = tid & 31;
    const int g = lane >> 2, tig = lane & 3;
    const int bm = blockIdx.y * 128, bn = blockIdx.x * 128;
    const int mbase = (wid >> 1) * 32, nbase = (wid & 1) * 64;

    const int BUF = 128 * SST;
    const uint32_t sbase = smem_u32(sm);

    const int lrow = tid >> 1, lk = (tid & 1) * 16;
    const float* Ag = A + (size_t)(bm + lrow) * 1024 + lk;
    const float* Bg = B + (size_t)(bn + lrow) * 1024 + lk;
    const uint32_t dstA = sbase + (uint32_t)(lrow * SST + lk) * 4;
    const uint32_t dstB = dstA + (uint32_t)BUF * 4;

    float acc[2][8][4];
#pragma unroll
    for (int mt = 0; mt < 2; mt++)
#pragma unroll
        for (int nt = 0; nt < 8; nt++)
#pragma unroll
            for (int q = 0; q < 4; q++) acc[mt][nt][q] = 0.f;

    {
#pragma unroll
        for (int j = 0; j < 4; j++) {
            cp_async16(dstA + j * 16, Ag + 4 * j);
            cp_async16(dstB + j * 16, Bg + 4 * j);
        }
        asm volatile("cp.async.commit_group;" ::: "memory");
    }

    for (int c = 0; c < 32; ++c) {
        if (c + 1 < 32) {
            const int st = (c + 1) & 1;
            const float* ag = Ag + (c + 1) * 32;
            const float* bg = Bg + (c + 1) * 32;
            const uint32_t off = (uint32_t)(st * 2 * BUF) * 4;
#pragma unroll
            for (int j = 0; j < 4; j++) {
                cp_async16(dstA + off + j * 16, ag + 4 * j);
                cp_async16(dstB + off + j * 16, bg + 4 * j);
            }
            asm volatile("cp.async.commit_group;" ::: "memory");
            asm volatile("cp.async.wait_group 1;" ::: "memory");
        } else {
            asm volatile("cp.async.wait_group 0;" ::: "memory");
        }
        __syncthreads();

        const float* As_ = sm + (c & 1) * 2 * BUF;
        const float* Bs_ = As_ + BUF;
#pragma unroll
        for (int ks = 0; ks < 4; ks++) {
            const int k = ks * 8;
            uint32_t a[2][4];
#pragma unroll
            for (int mt = 0; mt < 2; mt++) {
                const float* ap = As_ + (mbase + mt * 16 + g) * SST + k + tig;
                a[mt][0] = __float_as_uint(ap[0]);
                a[mt][1] = __float_as_uint(ap[8 * SST]);
                a[mt][2] = __float_as_uint(ap[4]);
                a[mt][3] = __float_as_uint(ap[8 * SST + 4]);
            }
#pragma unroll
            for (int nt = 0; nt < 8; nt++) {
                const float* bp = Bs_ + (nbase + nt * 8 + g) * SST + k + tig;
                uint32_t b0 = __float_as_uint(bp[0]);
                uint32_t b1 = __float_as_uint(bp[4]);
                mma_m16n8k8(acc[0][nt], a[0], b0, b1);
                mma_m16n8k8(acc[1][nt], a[1], b0, b1);
            }
        }
        __syncthreads();
    }

#pragma unroll
    for (int mt = 0; mt < 2; mt++) {
        const size_t r0 = (size_t)(bm + mbase + mt * 16 + g) * 1024;
#pragma unroll
        for (int nt = 0; nt < 8; nt++) {
            const int col = bn + nbase + nt * 8 + 2 * tig;
            float2 bb = *(const float2*)&bias[col];
            float2 v0 = make_float2(acc[mt][nt][0] + bb.x, acc[mt][nt][1] + bb.y);
            float2 v1 = make_float2(acc[mt][nt][2] + bb.x, acc[mt][nt][3] + bb.y);
            *(float2*)&C[r0 + col] = v0;
            *(float2*)&C[r0 + 8 * 1024 + col] = v1;
        }
    }
}

// ---------------------------------------------------------------------------
// Persistent recurrence scan: round-13 core with
//  - coalesced batch-pair ring writes (128 writer threads, STG.64 runs)
//  - all-4-warps quarter polling (no named barrier)
// ---------------------------------------------------------------------------
__global__ void __launch_bounds__(512, 1) rnn_scan(const float* __restrict__ Wih)
{
    extern __shared__ float smf[];
    float* wsm = smf;                    // [1024 k][16 n] n-major (64 KB)
    ull* red = (ull*)(smf + 16384);      // [16 w][8 c][32 lane] (32 KB)

    const int tid  = threadIdx.x;
    const int warp = tid >> 5, lane = tid & 31;
    const int bq = lane & 7;             // 4-batch group within 32
    const int nq = lane >> 3;            // 4-n group within 16
    const int kbase = warp * 64;
    const int Q = warp >> 2;             // k-quarter this warp consumes
    const int grp = blockIdx.x & 1;      // batch group
    const int cid = blockIdx.x >> 1;     // CTA id within group (0..63)
    const int NB0 = cid * 16;
    const int B0  = grp * 32;
    unsigned* myctr = &g_qctr[grp * 4 + (cid >> 4)][0];
    unsigned* rdctr = &g_qctr[grp * 4 + Q][0];

    for (int idx = tid; idx < 16384; idx += 512) {
        int n = idx >> 10, k = idx & 1023;
        wsm[k * 16 + n] = Wih[(size_t)(NB0 + n) * 2048 + 1024 + k];
    }

    // Writer decode (tid < 128): thread owns batch-pair x n-pair.
    const int wq = tid & 15, j2 = tid >> 4;            // valid for tid < 128
    const int b0 = B0 + 2 * wq;                        // even batch (global)
    const int n0 = NB0 + (j2 >> 1) * 4 + (j2 & 1) * 2; // even n (global)
    const int i0 = (2 * wq) & 3;                       // red i for b0 (i1=i0+1)
    const int lp = (wq >> 1) + 8 * (j2 >> 1);          // red lane
    const int c0 = i0 * 2 + (j2 & 1);                  // red column for b0
    const size_t pbA = ((size_t)b0 * NS) * NF + n0;
    const size_t pbB = pbA + (size_t)NS * NF;          // batch b0+1

    __syncthreads();

    float2 pr0 = make_float2(0.f, 0.f), pr1 = make_float2(0.f, 0.f);
    if (tid < 128) {
        pr0 = *(const float2*)&g_P[pbA];
        pr1 = *(const float2*)&g_P[pbB];
    }

    for (int s = 0; s < NS; ++s) {
        // Quarter gate: every warp of quarter Q polls its producers' counter.
        if (s > 0) {
            const unsigned tgt = (unsigned)s << 4;
            unsigned v;
            do {
                asm volatile("ld.acquire.gpu.global.u32 %0, [%1];"
                             : "=r"(v) : "l"(rdctr));
            } while (v < tgt);
        }

        const float* __restrict__ hq =
            g_ring + ((s + 1) & 1) * (1032 * 64) + B0 + 4 * bq;

        ull acc[4][2];
#pragma unroll
        for (int i = 0; i < 4; i++) { acc[i][0] = 0ull; acc[i][1] = 0ull; }

        float4 pf[8];
#pragma unroll
        for (int j = 0; j < 8; ++j)
            pf[j] = *(const float4*)(hq + (kbase + j) * 64);
#pragma unroll 8
        for (int kk = 0; kk < 64; ++kk) {
            const int slot = kk & 7;
            float4 h = pf[slot];
            pf[slot] = *(const float4*)(hq + (kbase + kk + 8) * 64);
            ulonglong2 w = *(const ulonglong2*)(wsm + (kbase + kk) * 16 + 4 * nq);
            ull h0d = pack2(h.x), h1d = pack2(h.y);
            ull h2d = pack2(h.z), h3d = pack2(h.w);
            fma2(acc[0][0], h0d, w.x); fma2(acc[0][1], h0d, w.y);
            fma2(acc[1][0], h1d, w.x); fma2(acc[1][1], h1d, w.y);
            fma2(acc[2][0], h2d, w.x); fma2(acc[2][1], h2d, w.y);
            fma2(acc[3][0], h3d, w.x); fma2(acc[3][1], h3d, w.y);
        }

#pragma unroll
        for (int i = 0; i < 4; i++)
#pragma unroll
            for (int p = 0; p < 2; p++)
                red[((warp * 8) + (i * 2 + p)) * 32 + lane] = acc[i][p];
        __syncthreads();                        // sync1: partials visible

        float v00 = 0.f, v01 = 0.f, v10 = 0.f, v11 = 0.f;
        if (tid < 128) {
            ull s0 = red[c0 * 32 + lp];                 // b0, (n0,n0+1)
            ull s1 = red[(c0 + 2) * 32 + lp];           // b0+1
#pragma unroll
            for (int w2 = 1; w2 < 16; ++w2) {
                add2(s0, red[(w2 * 8 + c0) * 32 + lp]);
                add2(s1, red[(w2 * 8 + c0 + 2) * 32 + lp]);
            }
            float2 f0 = unpack2(s0);
            float2 f1 = unpack2(s1);
            v00 = tanhf(f0.x + pr0.x);   // (b0, n0)
            v01 = tanhf(f0.y + pr0.y);   // (b0, n0+1)
            v10 = tanhf(f1.x + pr1.x);   // (b0+1, n0)
            v11 = tanhf(f1.y + pr1.y);   // (b0+1, n0+1)
            // Coalesced ring writes: batch-pair float2 per n row.
            float* rc = g_ring + (s & 1) * (1032 * 64);
            *(float2*)(rc + n0 * 64 + b0)       = make_float2(v00, v10);
            *(float2*)(rc + (n0 + 1) * 64 + b0) = make_float2(v01, v11);
        }
        __syncthreads();   // sync2: ring writes done; red safe for next STS

        if (s != NS - 1) {
            if (tid == 0) {
                asm volatile("red.release.gpu.global.add.u32 [%0], %1;"
                             :: "l"(myctr), "r"(1u) : "memory");
            }
            // Overlapped with other CTAs' progress: g_H + g_P prefetch.
            if (tid < 128) {
                *(float2*)&g_H[pbA + (size_t)s * NF] =
                    make_float2(tf32r(v00), tf32r(v01));
                *(float2*)&g_H[pbB + (size_t)s * NF] =
                    make_float2(tf32r(v10), tf32r(v11));
                pr0 = *(const float2*)&g_P[pbA + (size_t)(s + 1) * NF];
                pr1 = *(const float2*)&g_P[pbB + (size_t)(s + 1) * NF];
            }
        } else {
            if (tid < 128) {
                *(float2*)&g_H[pbA + (size_t)s * NF] =
                    make_float2(tf32r(v00), tf32r(v01));
                *(float2*)&g_H[pbB + (size_t)s * NF] =
                    make_float2(tf32r(v10), tf32r(v11));
            }
        }
    }
}

extern "C" void kernel_launch(void* const* d_in, const int* in_sizes, int n_in,
                              void* d_out, int out_size)
{
    const float* x   = (const float*)d_in[0];
    const float* h0  = (const float*)d_in[1];
    const float* Wih = (const float*)d_in[2];
    const float* bih = (const float*)d_in[3];
    const float* Who = (const float*)d_in[4];
    const float* bho = (const float*)d_in[5];
    float* out = (float*)d_out;

    float *pP = nullptr, *pH = nullptr, *pWx = nullptr, *pWo = nullptr;
    cudaGetSymbolAddress((void**)&pP, g_P);
    cudaGetSymbolAddress((void**)&pH, g_H);
    cudaGetSymbolAddress((void**)&pWx, g_Wx);
    cudaGetSymbolAddress((void**)&pWo, g_Who);

    const int GEMM_SMEM = 4 * 128 * SST * 4;   // 73728 B
    const int SCAN_SMEM = 98304;

    static bool attr_done = false;
    if (!attr_done) {
        cudaFuncSetAttribute(rnn_scan, cudaFuncAttributeMaxDynamicSharedMemorySize, SCAN_SMEM);
        cudaFuncSetAttribute(gemm_mma, cudaFuncAttributeMaxDynamicSharedMemorySize, GEMM_SMEM);
        attr_done = true;
    }

    // user idx 0: fused init
    fused_init<<<32768, 256>>>(x, Wih, Who, h0);
    // user idx 1: x_proj = x_r @ W_x^T + b_ih -> g_P
    gemm_mma<<<dim3(8, 256), 256, GEMM_SMEM>>>(pH, pWx, bih, pP);
    // user idx 2: pad so profiler (user idx 3) hits the scan
    knop<<<1, 32>>>();
    // user idx 3: persistent recurrence scan  <-- ncu capture
    rnn_scan<<<128, 512, SCAN_SMEM>>>(Wih);
    // user idx 4: out = h_r @ W_ho^T + b_ho
    gemm_mma<<<dim3(8, 256), 256, GEMM_SMEM>>>(pH, pWo, bho, out);
}

// round 15
// speedup vs baseline: 1.0136x; 1.0136x over previous
#include <cuda_runtime.h>
#include <math.h>
#include <cstdint>

#define NB 64
#define NS 512
#define NF 1024
#define SST 36   // gemm smem row stride in floats

static __device__ float g_P[NB * NS * NF];      // x_proj, [b][s][h]
static __device__ float g_H[NB * NS * NF];      // x_rounded, then tf32-rounded h
static __device__ float g_Wx[NF * NF];          // tf32-rounded W_x
static __device__ float g_Who[NF * NF];         // tf32-rounded W_ho
static __device__ float g_ring[2 * 1032 * 64];  // transposed h ring [slot][k][b]
static __device__ unsigned g_qctr[2][4];        // per-(group, k-quarter) arrivals

typedef unsigned long long ull;

__device__ __forceinline__ ull pack2(float x) {
    ull r; asm("mov.b64 %0, {%1, %1};" : "=l"(r) : "f"(x)); return r;
}
__device__ __forceinline__ float2 unpack2(ull v) {
    float2 r; asm("mov.b64 {%0, %1}, %2;" : "=f"(r.x), "=f"(r.y) : "l"(v)); return r;
}
__device__ __forceinline__ void fma2(ull& d, ull a, ull b) {
    asm("fma.rn.f32x2 %0, %1, %2, %0;" : "+l"(d) : "l"(a), "l"(b));
}
__device__ __forceinline__ float tf32r(float x) {
    float r; asm("cvt.rna.tf32.f32 %0, %1;" : "=f"(r) : "f"(x)); return r;
}
__device__ __forceinline__ uint32_t smem_u32(const void* p) {
    uint32_t a;
    asm("{ .reg .u64 t; cvta.to.shared.u64 t, %1; cvt.u32.u64 %0, t; }" : "=r"(a) : "l"(p));
    return a;
}
__device__ __forceinline__ void cp_async16(uint32_t dst, const void* src) {
    asm volatile("cp.async.cg.shared.global [%0], [%1], 16;" :: "r"(dst), "l"(src) : "memory");
}
__device__ __forceinline__ void mma_m16n8k8(float* c, const uint32_t* a,
                                            uint32_t b0, uint32_t b1) {
    asm volatile(
        "mma.sync.aligned.m16n8k8.row.col.f32.tf32.tf32.f32 "
        "{%0,%1,%2,%3}, {%4,%5,%6,%7}, {%8,%9}, {%0,%1,%2,%3};"
        : "+f"(c[0]), "+f"(c[1]), "+f"(c[2]), "+f"(c[3])
        : "r"(a[0]), "r"(a[1]), "r"(a[2]), "r"(a[3]), "r"(b0), "r"(b1));
}

__global__ void knop() {}

// ---------------------------------------------------------------------------
// Fused init: tf32-round x -> g_H, round weights, ring slot 1 <- h0^T, ctrs.
// ---------------------------------------------------------------------------
__global__ void fused_init(const float* __restrict__ x,
                           const float* __restrict__ Wih,
                           const float* __restrict__ Who,
                           const float* __restrict__ h0)
{
    int i = blockIdx.x * 256 + threadIdx.x;   // float4 idx
    float4 v = ((const float4*)x)[i];
    v.x = tf32r(v.x); v.y = tf32r(v.y); v.z = tf32r(v.z); v.w = tf32r(v.w);
    ((float4*)g_H)[i] = v;

    if (i < NF * NF) {
        int n = i >> 10, k = i & 1023;
        g_Wx[i]  = tf32r(Wih[(size_t)n * 2048 + k]);
        g_Who[i] = tf32r(Who[i]);
    }
    if (i < 65536) {
        int k = i >> 6, b = i & 63;
        g_ring[1032 * 64 + k * 64 + b] = h0[b * 1024 + k];
    }
    if (i < 8) ((unsigned*)g_qctr)[i] = 0u;
}

// ---------------------------------------------------------------------------
// tf32 mma.sync GEMM v3: same tile/fragment math as the proven round-7
// kernel, but 3-stage cp.async pipeline with ONE __syncthreads per k-chunk.
// Issue into stage (c+2)%3 happens AFTER the barrier: that buffer was last
// read at chunk c-1, and the barrier orders all iter-(c-1) reads before the
// new writes. SMEM: 3 stages x (A+B) = 110592 B; 2 CTAs/SM (221 KB <= 228).
// ---------------------------------------------------------------------------
__global__ void __launch_bounds__(256, 2) gemm_mma(
    const float* __restrict__ A, const float* __restrict__ B,
    const float* __restrict__ bias, float* __restrict__ C)
{
    extern __shared__ float sm[];
    const int tid = threadIdx.x;
    const int wid = tid >> 5, lane = tid & 31;
    const int g = lane >> 2, tig = lane & 3;
    const int bm = blockIdx.y * 128, bn = blockIdx.x * 128;
    const int mbase = (wid >> 1) * 32, nbase = (wid & 1) * 64;

    const int BUF = 128 * SST;       // floats per half-stage (A or B)
    const int STG = 2 * BUF;         // floats per stage
    const uint32_t sbase = smem_u32(sm);

    const int lrow = tid >> 1, lk = (tid & 1) * 16;
    const float* Ag = A + (size_t)(bm + lrow) * 1024 + lk;
    const float* Bg = B + (size_t)(bn + lrow) * 1024 + lk;
    const uint32_t dstA = sbase + (uint32_t)(lrow * SST + lk) * 4;
    const uint32_t dstB = dstA + (uint32_t)BUF * 4;

    float acc[2][8][4];
#pragma unroll
    for (int mt = 0; mt < 2; mt++)
#pragma unroll
        for (int nt = 0; nt < 8; nt++)
#pragma unroll
            for (int q = 0; q < 4; q++) acc[mt][nt][q] = 0.f;

    // prologue: issue chunks 0 and 1 into stages 0 and 1
#pragma unroll
    for (int pc = 0; pc < 2; pc++) {
        const float* ag = Ag + pc * 32;
        const float* bg = Bg + pc * 32;
        const uint32_t off = (uint32_t)(pc * STG) * 4;
#pragma unroll
        for (int j = 0; j < 4; j++) {
            cp_async16(dstA + off + j * 16, ag + 4 * j);
            cp_async16(dstB + off + j * 16, bg + 4 * j);
        }
        asm volatile("cp.async.commit_group;" ::: "memory");
    }

    for (int c = 0; c < 32; ++c) {
        if (c + 2 < 32) {
            asm volatile("cp.async.wait_group 1;" ::: "memory");
        } else {
            asm volatile("cp.async.wait_group 0;" ::: "memory");
        }
        __syncthreads();

        if (c + 2 < 32) {
            const int st = (c + 2) % 3;
            const float* ag = Ag + (c + 2) * 32;
            const float* bg = Bg + (c + 2) * 32;
            const uint32_t off = (uint32_t)(st * STG) * 4;
#pragma unroll
            for (int j = 0; j < 4; j++) {
                cp_async16(dstA + off + j * 16, ag + 4 * j);
                cp_async16(dstB + off + j * 16, bg + 4 * j);
            }
            asm volatile("cp.async.commit_group;" ::: "memory");
        }

        const float* As_ = sm + (c % 3) * STG;
        const float* Bs_ = As_ + BUF;
#pragma unroll
        for (int ks = 0; ks < 4; ks++) {
            const int k = ks * 8;
            uint32_t a[2][4];
#pragma unroll
            for (int mt = 0; mt < 2; mt++) {
                const float* ap = As_ + (mbase + mt * 16 + g) * SST + k + tig;
                a[mt][0] = __float_as_uint(ap[0]);
                a[mt][1] = __float_as_uint(ap[8 * SST]);
                a[mt][2] = __float_as_uint(ap[4]);
                a[mt][3] = __float_as_uint(ap[8 * SST + 4]);
            }
#pragma unroll
            for (int nt = 0; nt < 8; nt++) {
                const float* bp = Bs_ + (nbase + nt * 8 + g) * SST + k + tig;
                uint32_t b0 = __float_as_uint(bp[0]);
                uint32_t b1 = __float_as_uint(bp[4]);
                mma_m16n8k8(acc[0][nt], a[0], b0, b1);
                mma_m16n8k8(acc[1][nt], a[1], b0, b1);
            }
        }
        // no trailing sync: next write targets stage (c+3)%3 = (c)%3 only
        // after the NEXT iteration's barrier.
    }

#pragma unroll
    for (int mt = 0; mt < 2; mt++) {
        const size_t r0 = (size_t)(bm + mbase + mt * 16 + g) * 1024;
#pragma unroll
        for (int nt = 0; nt < 8; nt++) {
            const int col = bn + nbase + nt * 8 + 2 * tig;
            float2 bb = *(const float2*)&bias[col];
            float2 v0 = make_float2(acc[mt][nt][0] + bb.x, acc[mt][nt][1] + bb.y);
            float2 v1 = make_float2(acc[mt][nt][2] + bb.x, acc[mt][nt][3] + bb.y);
            *(float2*)&C[r0 + col] = v0;
            *(float2*)&C[r0 + 8 * 1024 + col] = v1;
        }
    }
}

// ---------------------------------------------------------------------------
// Persistent recurrence scan — ROUND 13 VERSION VERBATIM (best: 2726 us).
// Quarter gates: warp 4Q polls, named bar Q+1 rendezvous.
// ---------------------------------------------------------------------------
__global__ void __launch_bounds__(512, 1) rnn_scan(const float* __restrict__ Wih)
{
    extern __shared__ float smf[];
    float* wsm = smf;                    // [1024 k][16 n] n-major (64 KB)
    ull* red = (ull*)(smf + 16384);      // [16 w][8 q][32 lane] (32 KB)

    const int tid  = threadIdx.x;
    const int warp = tid >> 5, lane = tid & 31;
    const int bq = lane & 7;             // 4-batch group within 32
    const int nq = lane >> 3;            // 4-n group within 16
    const int kbase = warp * 64;
    const int Q = warp >> 2;             // k-quarter this warp consumes
    const int grp = blockIdx.x & 1;      // batch group
    const int cid = blockIdx.x >> 1;     // CTA id within group (0..63)
    const int NB0 = cid * 16;
    const int B0  = grp * 32;
    unsigned* myctr = &g_qctr[grp][cid >> 4];
    unsigned* rdctr = &g_qctr[grp][Q];

    for (int idx = tid; idx < 16384; idx += 512) {
        int n = idx >> 10, k = idx & 1023;
        wsm[k * 16 + n] = Wih[(size_t)(NB0 + n) * 2048 + 1024 + k];
    }

    const int rq = tid >> 5, rl = tid & 31;            // valid for tid < 256
    const int rb = B0 + 4 * (rl & 7) + (rq >> 1);      // batch
    const int rn = NB0 + 4 * (rl >> 3) + 2 * (rq & 1); // even n
    const size_t pb = ((size_t)rb * NS) * NF + rn;

    __syncthreads();

    float2 pr = make_float2(0.f, 0.f);
    if (tid < 256) pr = *(const float2*)&g_P[pb];

    for (int s = 0; s < NS; ++s) {
        if (s > 0) {
            if ((warp & 3) == 0) {
                const unsigned tgt = (unsigned)s << 4;
                unsigned v;
                do {
                    asm volatile("ld.acquire.gpu.global.u32 %0, [%1];"
                                 : "=r"(v) : "l"(rdctr));
                } while (v < tgt);
            }
            asm volatile("bar.sync %0, 128;" :: "r"(Q + 1) : "memory");
        }

        const float* __restrict__ hq =
            g_ring + ((s + 1) & 1) * (1032 * 64) + B0 + 4 * bq;

        ull acc[4][2];
#pragma unroll
        for (int i = 0; i < 4; i++) { acc[i][0] = 0ull; acc[i][1] = 0ull; }

        float4 pf[8];
#pragma unroll
        for (int j = 0; j < 8; ++j)
            pf[j] = *(const float4*)(hq + (kbase + j) * 64);
#pragma unroll 8
        for (int kk = 0; kk < 64; ++kk) {
            const int slot = kk & 7;
            float4 h = pf[slot];
            pf[slot] = *(const float4*)(hq + (kbase + kk + 8) * 64);
            ulonglong2 w = *(const ulonglong2*)(wsm + (kbase + kk) * 16 + 4 * nq);
            ull h0d = pack2(h.x), h1d = pack2(h.y);
            ull h2d = pack2(h.z), h3d = pack2(h.w);
            fma2(acc[0][0], h0d, w.x); fma2(acc[0][1], h0d, w.y);
            fma2(acc[1][0], h1d, w.x); fma2(acc[1][1], h1d, w.y);
            fma2(acc[2][0], h2d, w.x); fma2(acc[2][1], h2d, w.y);
            fma2(acc[3][0], h3d, w.x); fma2(acc[3][1], h3d, w.y);
        }

#pragma unroll
        for (int i = 0; i < 4; i++)
#pragma unroll
            for (int p = 0; p < 2; p++)
                red[((warp * 8) + (i * 2 + p)) * 32 + lane] = acc[i][p];
        __syncthreads();                        // sync1: partials visible

        float r0 = 0.f, r1 = 0.f;
        if (tid < 256) {
            float sx = 0.f, sy = 0.f;
#pragma unroll
            for (int w2 = 0; w2 < 16; ++w2) {
                float2 v = unpack2(red[(w2 * 8 + rq) * 32 + rl]);
                sx += v.x; sy += v.y;
            }
            r0 = tanhf(sx + pr.x);
            r1 = tanhf(sy + pr.y);
            float* rc = g_ring + (s & 1) * (1032 * 64);
            rc[rn * 64 + rb] = r0;
            rc[(rn + 1) * 64 + rb] = r1;
        }
        __syncthreads();   // sync2: ring writes done; red safe for next STS

        if (s != NS - 1) {
            if (tid == 0) {
                asm volatile("red.release.gpu.global.add.u32 [%0], %1;"
                             :: "l"(myctr), "r"(1u) : "memory");
            }
            if (tid < 256) {
                *(float2*)&g_H[pb + (size_t)s * NF] =
                    make_float2(tf32r(r0), tf32r(r1));
                pr = *(const float2*)&g_P[pb + (size_t)(s + 1) * NF];
            }
        } else {
            if (tid < 256) {
                *(float2*)&g_H[pb + (size_t)s * NF] =
                    make_float2(tf32r(r0), tf32r(r1));
            }
        }
    }
}

extern "C" void kernel_launch(void* const* d_in, const int* in_sizes, int n_in,
                              void* d_out, int out_size)
{
    const float* x   = (const float*)d_in[0];
    const float* h0  = (const float*)d_in[1];
    const float* Wih = (const float*)d_in[2];
    const float* bih = (const float*)d_in[3];
    const float* Who = (const float*)d_in[4];
    const float* bho = (const float*)d_in[5];
    float* out = (float*)d_out;

    float *pP = nullptr, *pH = nullptr, *pWx = nullptr, *pWo = nullptr;
    cudaGetSymbolAddress((void**)&pP, g_P);
    cudaGetSymbolAddress((void**)&pH, g_H);
    cudaGetSymbolAddress((void**)&pWx, g_Wx);
    cudaGetSymbolAddress((void**)&pWo, g_Who);

    const int GEMM_SMEM = 3 * 2 * 128 * SST * 4;   // 110592 B (3 stages)
    const int SCAN_SMEM = 98304;

    static bool attr_done = false;
    if (!attr_done) {
        cudaFuncSetAttribute(rnn_scan, cudaFuncAttributeMaxDynamicSharedMemorySize, SCAN_SMEM);
        cudaFuncSetAttribute(gemm_mma, cudaFuncAttributeMaxDynamicSharedMemorySize, GEMM_SMEM);
        attr_done = true;
    }

    // user idx 0: fused init
    fused_init<<<32768, 256>>>(x, Wih, Who, h0);
    // user idx 1: x_proj = x_r @ W_x^T + b_ih -> g_P
    gemm_mma<<<dim3(8, 256), 256, GEMM_SMEM>>>(pH, pWx, bih, pP);
    // user idx 2: pad so profiler (user idx 3) hits the scan
    knop<<<1, 32>>>();
    // user idx 3: persistent recurrence scan  <-- ncu capture
    rnn_scan<<<128, 512, SCAN_SMEM>>>(Wih);
    // user idx 4: out = h_r @ W_ho^T + b_ho
    gemm_mma<<<dim3(8, 256), 256, GEMM_SMEM>>>(pH, pWo, bho, out);
}

// round 16
// speedup vs baseline: 1.0320x; 1.0182x over previous
#include <cuda_runtime.h>
#include <math.h>
#include <cstdint>

#define NB 64
#define NS 512
#define NF 1024
#define SST 36   // gemm smem row stride in floats

static __device__ float g_P[NB * NS * NF];      // x_proj, [b][s][h]
static __device__ float g_H[NB * NS * NF];      // x_rounded, then tf32-rounded h
static __device__ float g_Wx[NF * NF];          // tf32-rounded W_x
static __device__ float g_Who[NF * NF];         // tf32-rounded W_ho
static __device__ float g_ring[2 * 1032 * 64];  // transposed h ring [slot][k][b]
static __device__ unsigned g_qctr[16][32];      // (grp*4+Q) counters, line apart

typedef unsigned long long ull;

__device__ __forceinline__ ull pack2(float x) {
    ull r; asm("mov.b64 %0, {%1, %1};" : "=l"(r) : "f"(x)); return r;
}
__device__ __forceinline__ float2 unpack2(ull v) {
    float2 r; asm("mov.b64 {%0, %1}, %2;" : "=f"(r.x), "=f"(r.y) : "l"(v)); return r;
}
__device__ __forceinline__ void fma2(ull& d, ull a, ull b) {
    asm("fma.rn.f32x2 %0, %1, %2, %0;" : "+l"(d) : "l"(a), "l"(b));
}
__device__ __forceinline__ float tf32r(float x) {
    float r; asm("cvt.rna.tf32.f32 %0, %1;" : "=f"(r) : "f"(x)); return r;
}
__device__ __forceinline__ uint32_t smem_u32(const void* p) {
    uint32_t a;
    asm("{ .reg .u64 t; cvta.to.shared.u64 t, %1; cvt.u32.u64 %0, t; }" : "=r"(a) : "l"(p));
    return a;
}
__device__ __forceinline__ void cp_async16(uint32_t dst, const void* src) {
    asm volatile("cp.async.cg.shared.global [%0], [%1], 16;" :: "r"(dst), "l"(src) : "memory");
}
__device__ __forceinline__ void mma_m16n8k8(float* c, const uint32_t* a,
                                            uint32_t b0, uint32_t b1) {
    asm volatile(
        "mma.sync.aligned.m16n8k8.row.col.f32.tf32.tf32.f32 "
        "{%0,%1,%2,%3}, {%4,%5,%6,%7}, {%8,%9}, {%0,%1,%2,%3};"
        : "+f"(c[0]), "+f"(c[1]), "+f"(c[2]), "+f"(c[3])
        : "r"(a[0]), "r"(a[1]), "r"(a[2]), "r"(a[3]), "r"(b0), "r"(b1));
}

__global__ void knop() {}

// ---------------------------------------------------------------------------
// Fused init: tf32-round x -> g_H, round weights, ring slot 1 <- h0^T, ctrs.
// ---------------------------------------------------------------------------
__global__ void fused_init(const float* __restrict__ x,
                           const float* __restrict__ Wih,
                           const float* __restrict__ Who,
                           const float* __restrict__ h0)
{
    int i = blockIdx.x * 256 + threadIdx.x;   // float4 idx
    float4 v = ((const float4*)x)[i];
    v.x = tf32r(v.x); v.y = tf32r(v.y); v.z = tf32r(v.z); v.w = tf32r(v.w);
    ((float4*)g_H)[i] = v;

    if (i < NF * NF) {
        int n = i >> 10, k = i & 1023;
        g_Wx[i]  = tf32r(Wih[(size_t)n * 2048 + k]);
        g_Who[i] = tf32r(Who[i]);
    }
    if (i < 65536) {
        int k = i >> 6, b = i & 63;
        g_ring[1032 * 64 + k * 64 + b] = h0[b * 1024 + k];
    }
    if (i < 512) ((unsigned*)g_qctr)[i] = 0u;
}

// ---------------------------------------------------------------------------
// tf32 mma.sync GEMM v3 (round-15: 3-stage cp.async, one sync per chunk).
// ---------------------------------------------------------------------------
__global__ void __launch_bounds__(256, 2) gemm_mma(
    const float* __restrict__ A, const float* __restrict__ B,
    const float* __restrict__ bias, float* __restrict__ C)
{
    extern __shared__ float sm[];
    const int tid = threadIdx.x;
    const int wid = tid >> 5, lane = tid & 31;
    const int g = lane >> 2, tig = lane & 3;
    const int bm = blockIdx.y * 128, bn = blockIdx.x * 128;
    const int mbase = (wid >> 1) * 32, nbase = (wid & 1) * 64;

    const int BUF = 128 * SST;
    const int STG = 2 * BUF;
    const uint32_t sbase = smem_u32(sm);

    const int lrow = tid >> 1, lk = (tid & 1) * 16;
    const float* Ag = A + (size_t)(bm + lrow) * 1024 + lk;
    const float* Bg = B + (size_t)(bn + lrow) * 1024 + lk;
    const uint32_t dstA = sbase + (uint32_t)(lrow * SST + lk) * 4;
    const uint32_t dstB = dstA + (uint32_t)BUF * 4;

    float acc[2][8][4];
#pragma unroll
    for (int mt = 0; mt < 2; mt++)
#pragma unroll
        for (int nt = 0; nt < 8; nt++)
#pragma unroll
            for (int q = 0; q < 4; q++) acc[mt][nt][q] = 0.f;

#pragma unroll
    for (int pc = 0; pc < 2; pc++) {
        const float* ag = Ag + pc * 32;
        const float* bg = Bg + pc * 32;
        const uint32_t off = (uint32_t)(pc * STG) * 4;
#pragma unroll
        for (int j = 0; j < 4; j++) {
            cp_async16(dstA + off + j * 16, ag + 4 * j);
            cp_async16(dstB + off + j * 16, bg + 4 * j);
        }
        asm volatile("cp.async.commit_group;" ::: "memory");
    }

    for (int c = 0; c < 32; ++c) {
        if (c + 2 < 32) {
            asm volatile("cp.async.wait_group 1;" ::: "memory");
        } else {
            asm volatile("cp.async.wait_group 0;" ::: "memory");
        }
        __syncthreads();

        if (c + 2 < 32) {
            const int st = (c + 2) % 3;
            const float* ag = Ag + (c + 2) * 32;
            const float* bg = Bg + (c + 2) * 32;
            const uint32_t off = (uint32_t)(st * STG) * 4;
#pragma unroll
            for (int j = 0; j < 4; j++) {
                cp_async16(dstA + off + j * 16, ag + 4 * j);
                cp_async16(dstB + off + j * 16, bg + 4 * j);
            }
            asm volatile("cp.async.commit_group;" ::: "memory");
        }

        const float* As_ = sm + (c % 3) * STG;
        const float* Bs_ = As_ + BUF;
#pragma unroll
        for (int ks = 0; ks < 4; ks++) {
            const int k = ks * 8;
            uint32_t a[2][4];
#pragma unroll
            for (int mt = 0; mt < 2; mt++) {
                const float* ap = As_ + (mbase + mt * 16 + g) * SST + k + tig;
                a[mt][0] = __float_as_uint(ap[0]);
                a[mt][1] = __float_as_uint(ap[8 * SST]);
                a[mt][2] = __float_as_uint(ap[4]);
                a[mt][3] = __float_as_uint(ap[8 * SST + 4]);
            }
#pragma unroll
            for (int nt = 0; nt < 8; nt++) {
                const float* bp = Bs_ + (nbase + nt * 8 + g) * SST + k + tig;
                uint32_t b0 = __float_as_uint(bp[0]);
                uint32_t b1 = __float_as_uint(bp[4]);
                mma_m16n8k8(acc[0][nt], a[0], b0, b1);
                mma_m16n8k8(acc[1][nt], a[1], b0, b1);
            }
        }
    }

#pragma unroll
    for (int mt = 0; mt < 2; mt++) {
        const size_t r0 = (size_t)(bm + mbase + mt * 16 + g) * 1024;
#pragma unroll
        for (int nt = 0; nt < 8; nt++) {
            const int col = bn + nbase + nt * 8 + 2 * tig;
            float2 bb = *(const float2*)&bias[col];
            float2 v0 = make_float2(acc[mt][nt][0] + bb.x, acc[mt][nt][1] + bb.y);
            float2 v1 = make_float2(acc[mt][nt][2] + bb.x, acc[mt][nt][3] + bb.y);
            *(float2*)&C[r0 + col] = v0;
            *(float2*)&C[r0 + 8 * 1024 + col] = v1;
        }
    }
}

// ---------------------------------------------------------------------------
// Persistent recurrence scan, 4 batch-groups: 128 CTAs x 512 threads,
// 4 groups of 32 CTAs. Group g owns batches [16g, 16g+16); CTA owns 32 n.
// W_h slice n-major unduplicated in SMEM ([1024 k][32 n], 128 KB). Warp w
// reduces k in [64w, 64w+64); lane tile 4 batches (bq=lane&3) x 4 n
// (nq=lane>>2): 1 LDG.128 + 1 LDS.128 + 8 FFMA2 per kk (round-13 identical).
// Per-CTA ring read halves to 64 KB/step (fits 68 KB L1 carveout).
// Quarter gates: 8 producer CTAs per (group, quarter); warp 4Q polls,
// named bar Q+1 rendezvous (round-13 protocol).
// ---------------------------------------------------------------------------
__global__ void __launch_bounds__(512, 1) rnn_scan(const float* __restrict__ Wih)
{
    extern __shared__ float smf[];
    float* wsm = smf;                    // [1024 k][32 n] n-major (128 KB)
    ull* red = (ull*)(smf + 32768);      // [16 w][8 c][32 lane] (32 KB)

    const int tid  = threadIdx.x;
    const int warp = tid >> 5, lane = tid & 31;
    const int bq = lane & 3;             // 4-batch group within 16
    const int nq = lane >> 2;            // 4-n group within 32
    const int kbase = warp * 64;
    const int Q = warp >> 2;             // k-quarter this warp consumes
    const int grp = blockIdx.x & 3;      // batch group (0..3)
    const int cid = blockIdx.x >> 2;     // CTA id within group (0..31)
    const int NB0 = cid * 32;
    const int B0  = grp * 16;
    unsigned* myctr = &g_qctr[grp * 4 + (cid >> 3)][0];
    unsigned* rdctr = &g_qctr[grp * 4 + Q][0];

    for (int idx = tid; idx < 32768; idx += 512) {
        int n = idx >> 10, k = idx & 1023;
        wsm[k * 32 + n] = Wih[(size_t)(NB0 + n) * 2048 + 1024 + k];
    }

    // Writer decode (tid < 256): rq = red column, rl = red lane.
    const int rq = tid >> 5, rl = tid & 31;            // valid for tid < 256
    const int rb = B0 + 4 * (rl & 3) + (rq >> 1);      // batch (global)
    const int rn = NB0 + 4 * (rl >> 2) + 2 * (rq & 1); // even n (global)
    const size_t pb = ((size_t)rb * NS) * NF + rn;

    __syncthreads();

    float2 pr = make_float2(0.f, 0.f);
    if (tid < 256) pr = *(const float2*)&g_P[pb];

    for (int s = 0; s < NS; ++s) {
        if (s > 0) {
            if ((warp & 3) == 0) {
                const unsigned tgt = (unsigned)s << 3;   // 8 producers
                unsigned v;
                do {
                    asm volatile("ld.acquire.gpu.global.u32 %0, [%1];"
                                 : "=r"(v) : "l"(rdctr));
                } while (v < tgt);
            }
            asm volatile("bar.sync %0, 128;" :: "r"(Q + 1) : "memory");
        }

        const float* __restrict__ hq =
            g_ring + ((s + 1) & 1) * (1032 * 64) + B0 + 4 * bq;

        ull acc[4][2];
#pragma unroll
        for (int i = 0; i < 4; i++) { acc[i][0] = 0ull; acc[i][1] = 0ull; }

        float4 pf[8];
#pragma unroll
        for (int j = 0; j < 8; ++j)
            pf[j] = *(const float4*)(hq + (kbase + j) * 64);
#pragma unroll 8
        for (int kk = 0; kk < 64; ++kk) {
            const int slot = kk & 7;
            float4 h = pf[slot];
            pf[slot] = *(const float4*)(hq + (kbase + kk + 8) * 64);
            ulonglong2 w = *(const ulonglong2*)(wsm + (kbase + kk) * 32 + 4 * nq);
            ull h0d = pack2(h.x), h1d = pack2(h.y);
            ull h2d = pack2(h.z), h3d = pack2(h.w);
            fma2(acc[0][0], h0d, w.x); fma2(acc[0][1], h0d, w.y);
            fma2(acc[1][0], h1d, w.x); fma2(acc[1][1], h1d, w.y);
            fma2(acc[2][0], h2d, w.x); fma2(acc[2][1], h2d, w.y);
            fma2(acc[3][0], h3d, w.x); fma2(acc[3][1], h3d, w.y);
        }

#pragma unroll
        for (int i = 0; i < 4; i++)
#pragma unroll
            for (int p = 0; p < 2; p++)
                red[((warp * 8) + (i * 2 + p)) * 32 + lane] = acc[i][p];
        __syncthreads();                        // sync1: partials visible

        float r0 = 0.f, r1 = 0.f;
        if (tid < 256) {
            float sx = 0.f, sy = 0.f;
#pragma unroll
            for (int w2 = 0; w2 < 16; ++w2) {
                float2 v = unpack2(red[(w2 * 8 + rq) * 32 + rl]);
                sx += v.x; sy += v.y;
            }
            r0 = tanhf(sx + pr.x);
            r1 = tanhf(sy + pr.y);
            float* rc = g_ring + (s & 1) * (1032 * 64);
            rc[rn * 64 + rb] = r0;
            rc[(rn + 1) * 64 + rb] = r1;
        }
        __syncthreads();   // sync2: ring writes done; red safe for next STS

        if (s != NS - 1) {
            if (tid == 0) {
                asm volatile("red.release.gpu.global.add.u32 [%0], %1;"
                             :: "l"(myctr), "r"(1u) : "memory");
            }
            if (tid < 256) {
                *(float2*)&g_H[pb + (size_t)s * NF] =
                    make_float2(tf32r(r0), tf32r(r1));
                pr = *(const float2*)&g_P[pb + (size_t)(s + 1) * NF];
            }
        } else {
            if (tid < 256) {
                *(float2*)&g_H[pb + (size_t)s * NF] =
                    make_float2(tf32r(r0), tf32r(r1));
            }
        }
    }
}

extern "C" void kernel_launch(void* const* d_in, const int* in_sizes, int n_in,
                              void* d_out, int out_size)
{
    const float* x   = (const float*)d_in[0];
    const float* h0  = (const float*)d_in[1];
    const float* Wih = (const float*)d_in[2];
    const float* bih = (const float*)d_in[3];
    const float* Who = (const float*)d_in[4];
    const float* bho = (const float*)d_in[5];
    float* out = (float*)d_out;

    float *pP = nullptr, *pH = nullptr, *pWx = nullptr, *pWo = nullptr;
    cudaGetSymbolAddress((void**)&pP, g_P);
    cudaGetSymbolAddress((void**)&pH, g_H);
    cudaGetSymbolAddress((void**)&pWx, g_Wx);
    cudaGetSymbolAddress((void**)&pWo, g_Who);

    const int GEMM_SMEM = 3 * 2 * 128 * SST * 4;   // 110592 B
    const int SCAN_SMEM = 131072 + 32768;          // 163840 B

    static bool attr_done = false;
    if (!attr_done) {
        cudaFuncSetAttribute(rnn_scan, cudaFuncAttributeMaxDynamicSharedMemorySize, SCAN_SMEM);
        cudaFuncSetAttribute(gemm_mma, cudaFuncAttributeMaxDynamicSharedMemorySize, GEMM_SMEM);
        attr_done = true;
    }

    // user idx 0: fused init
    fused_init<<<32768, 256>>>(x, Wih, Who, h0);
    // user idx 1: x_proj = x_r @ W_x^T + b_ih -> g_P
    gemm_mma<<<dim3(8, 256), 256, GEMM_SMEM>>>(pH, pWx, bih, pP);
    // user idx 2: pad so profiler (user idx 3) hits the scan
    knop<<<1, 32>>>();
    // user idx 3: persistent recurrence scan  <-- ncu capture
    rnn_scan<<<128, 512, SCAN_SMEM>>>(Wih);
    // user idx 4: out = h_r @ W_ho^T + b_ho
    gemm_mma<<<dim3(8, 256), 256, GEMM_SMEM>>>(pH, pWo, bho, out);
}

// round 17
// speedup vs baseline: 1.0495x; 1.0169x over previous
#include <cuda_runtime.h>
#include <math.h>
#include <cstdint>

#define NB 64
#define NS 512
#define NF 1024
#define SST 36   // gemm smem row stride in floats

static __device__ float g_P[NB * NS * NF];      // x_proj, [b][s][h]
static __device__ float g_H[NB * NS * NF];      // hidden states (tf32-rounded)
static __device__ float g_Wx[NF * NF];          // tf32-rounded W_x
static __device__ float g_Who[NF * NF];         // tf32-rounded W_ho
static __device__ float g_ring[2 * 1032 * 64];  // transposed h ring [slot][k][b]
static __device__ unsigned g_qctr[16][32];      // (grp*4+Q) counters, line apart

typedef unsigned long long ull;

__device__ __forceinline__ ull pack2(float x) {
    ull r; asm("mov.b64 %0, {%1, %1};" : "=l"(r) : "f"(x)); return r;
}
__device__ __forceinline__ float2 unpack2(ull v) {
    float2 r; asm("mov.b64 {%0, %1}, %2;" : "=f"(r.x), "=f"(r.y) : "l"(v)); return r;
}
__device__ __forceinline__ void fma2(ull& d, ull a, ull b) {
    asm("fma.rn.f32x2 %0, %1, %2, %0;" : "+l"(d) : "l"(a), "l"(b));
}
__device__ __forceinline__ float tf32r(float x) {
    float r; asm("cvt.rna.tf32.f32 %0, %1;" : "=f"(r) : "f"(x)); return r;
}
__device__ __forceinline__ uint32_t smem_u32(const void* p) {
    uint32_t a;
    asm("{ .reg .u64 t; cvta.to.shared.u64 t, %1; cvt.u32.u64 %0, t; }" : "=r"(a) : "l"(p));
    return a;
}
__device__ __forceinline__ void cp_async16(uint32_t dst, const void* src) {
    asm volatile("cp.async.cg.shared.global [%0], [%1], 16;" :: "r"(dst), "l"(src) : "memory");
}
__device__ __forceinline__ void mma_m16n8k8(float* c, const uint32_t* a,
                                            uint32_t b0, uint32_t b1) {
    asm volatile(
        "mma.sync.aligned.m16n8k8.row.col.f32.tf32.tf32.f32 "
        "{%0,%1,%2,%3}, {%4,%5,%6,%7}, {%8,%9}, {%0,%1,%2,%3};"
        : "+f"(c[0]), "+f"(c[1]), "+f"(c[2]), "+f"(c[3])
        : "r"(a[0]), "r"(a[1]), "r"(a[2]), "r"(a[3]), "r"(b0), "r"(b1));
}

__global__ void knop() {}

// ---------------------------------------------------------------------------
// Fused init: round weights, ring slot 1 <- h0^T, counters. (x is rounded
// in-register inside gemm now.)
// ---------------------------------------------------------------------------
__global__ void fused_init(const float* __restrict__ Wih,
                           const float* __restrict__ Who,
                           const float* __restrict__ h0)
{
    int i = blockIdx.x * 256 + threadIdx.x;   // 0 .. 1M-1
    int n = i >> 10, k = i & 1023;
    g_Wx[i]  = tf32r(Wih[(size_t)n * 2048 + k]);
    g_Who[i] = tf32r(Who[i]);
    if (i < 65536) {
        int kk = i >> 6, b = i & 63;
        g_ring[1032 * 64 + kk * 64 + b] = h0[b * 1024 + kk];
    }
    if (i < 512) ((unsigned*)g_qctr)[i] = 0u;
}

// ---------------------------------------------------------------------------
// tf32 mma.sync GEMM v3 (3-stage cp.async) with in-register A rounding:
// cvt.rna.tf32 on A fragments (idempotent if A is already tf32-rounded).
// B must be pre-rounded (g_Wx / g_Who).
// ---------------------------------------------------------------------------
__global__ void __launch_bounds__(256, 2) gemm_mma(
    const float* __restrict__ A, const float* __restrict__ B,
    const float* __restrict__ bias, float* __restrict__ C)
{
    extern __shared__ float sm[];
    const int tid = threadIdx.x;
    const int wid = tid >> 5, lane = tid & 31;
    const int g = lane >> 2, tig = lane & 3;
    const int bm = blockIdx.y * 128, bn = blockIdx.x * 128;
    const int mbase = (wid >> 1) * 32, nbase = (wid & 1) * 64;

    const int BUF = 128 * SST;
    const int STG = 2 * BUF;
    const uint32_t sbase = smem_u32(sm);

    const int lrow = tid >> 1, lk = (tid & 1) * 16;
    const float* Ag = A + (size_t)(bm + lrow) * 1024 + lk;
    const float* Bg = B + (size_t)(bn + lrow) * 1024 + lk;
    const uint32_t dstA = sbase + (uint32_t)(lrow * SST + lk) * 4;
    const uint32_t dstB = dstA + (uint32_t)BUF * 4;

    float acc[2][8][4];
#pragma unroll
    for (int mt = 0; mt < 2; mt++)
#pragma unroll
        for (int nt = 0; nt < 8; nt++)
#pragma unroll
            for (int q = 0; q < 4; q++) acc[mt][nt][q] = 0.f;

#pragma unroll
    for (int pc = 0; pc < 2; pc++) {
        const float* ag = Ag + pc * 32;
        const float* bg = Bg + pc * 32;
        const uint32_t off = (uint32_t)(pc * STG) * 4;
#pragma unroll
        for (int j = 0; j < 4; j++) {
            cp_async16(dstA + off + j * 16, ag + 4 * j);
            cp_async16(dstB + off + j * 16, bg + 4 * j);
        }
        asm volatile("cp.async.commit_group;" ::: "memory");
    }

    for (int c = 0; c < 32; ++c) {
        if (c + 2 < 32) {
            asm volatile("cp.async.wait_group 1;" ::: "memory");
        } else {
            asm volatile("cp.async.wait_group 0;" ::: "memory");
        }
        __syncthreads();

        if (c + 2 < 32) {
            const int st = (c + 2) % 3;
            const float* ag = Ag + (c + 2) * 32;
            const float* bg = Bg + (c + 2) * 32;
            const uint32_t off = (uint32_t)(st * STG) * 4;
#pragma unroll
            for (int j = 0; j < 4; j++) {
                cp_async16(dstA + off + j * 16, ag + 4 * j);
                cp_async16(dstB + off + j * 16, bg + 4 * j);
            }
            asm volatile("cp.async.commit_group;" ::: "memory");
        }

        const float* As_ = sm + (c % 3) * STG;
        const float* Bs_ = As_ + BUF;
#pragma unroll
        for (int ks = 0; ks < 4; ks++) {
            const int k = ks * 8;
            uint32_t a[2][4];
#pragma unroll
            for (int mt = 0; mt < 2; mt++) {
                const float* ap = As_ + (mbase + mt * 16 + g) * SST + k + tig;
                a[mt][0] = __float_as_uint(tf32r(ap[0]));
                a[mt][1] = __float_as_uint(tf32r(ap[8 * SST]));
                a[mt][2] = __float_as_uint(tf32r(ap[4]));
                a[mt][3] = __float_as_uint(tf32r(ap[8 * SST + 4]));
            }
#pragma unroll
            for (int nt = 0; nt < 8; nt++) {
                const float* bp = Bs_ + (nbase + nt * 8 + g) * SST + k + tig;
                uint32_t b0 = __float_as_uint(bp[0]);
                uint32_t b1 = __float_as_uint(bp[4]);
                mma_m16n8k8(acc[0][nt], a[0], b0, b1);
                mma_m16n8k8(acc[1][nt], a[1], b0, b1);
            }
        }
    }

#pragma unroll
    for (int mt = 0; mt < 2; mt++) {
        const size_t r0 = (size_t)(bm + mbase + mt * 16 + g) * 1024;
#pragma unroll
        for (int nt = 0; nt < 8; nt++) {
            const int col = bn + nbase + nt * 8 + 2 * tig;
            float2 bb = *(const float2*)&bias[col];
            float2 v0 = make_float2(acc[mt][nt][0] + bb.x, acc[mt][nt][1] + bb.y);
            float2 v1 = make_float2(acc[mt][nt][2] + bb.x, acc[mt][nt][3] + bb.y);
            *(float2*)&C[r0 + col] = v0;
            *(float2*)&C[r0 + 8 * 1024 + col] = v1;
        }
    }
}

// ---------------------------------------------------------------------------
// Persistent recurrence scan (round-16 core) with:
//  - double-buffered reduction SMEM (parity-indexed; 64 KB total)
//  - NO trailing full-CTA barrier: writers (warps 0-7) rendezvous on named
//    bar 5 (256 threads) before tid-0's release-add; warps 8-15 proceed
//    straight from sync1 to their quarter poll + k-loop.
// Happens-before chain: ring STG -> bar.sync 5 -> release-add -> remote
// acquire-load -> remote ring reads (same pattern as before, narrower bar).
// ---------------------------------------------------------------------------
__global__ void __launch_bounds__(512, 1) rnn_scan(const float* __restrict__ Wih)
{
    extern __shared__ float smf[];
    float* wsm = smf;                    // [1024 k][32 n] n-major (128 KB)
    ull* redb = (ull*)(smf + 32768);     // 2 x [16 w][8 c][32 lane] (64 KB)

    const int tid  = threadIdx.x;
    const int warp = tid >> 5, lane = tid & 31;
    const int bq = lane & 3;             // 4-batch group within 16
    const int nq = lane >> 2;            // 4-n group within 32
    const int kbase = warp * 64;
    const int Q = warp >> 2;             // k-quarter this warp consumes
    const int grp = blockIdx.x & 3;      // batch group (0..3)
    const int cid = blockIdx.x >> 2;     // CTA id within group (0..31)
    const int NB0 = cid * 32;
    const int B0  = grp * 16;
    unsigned* myctr = &g_qctr[grp * 4 + (cid >> 3)][0];
    unsigned* rdctr = &g_qctr[grp * 4 + Q][0];

    for (int idx = tid; idx < 32768; idx += 512) {
        int n = idx >> 10, k = idx & 1023;
        wsm[k * 32 + n] = Wih[(size_t)(NB0 + n) * 2048 + 1024 + k];
    }

    const int rq = tid >> 5, rl = tid & 31;            // valid for tid < 256
    const int rb = B0 + 4 * (rl & 3) + (rq >> 1);      // batch (global)
    const int rn = NB0 + 4 * (rl >> 2) + 2 * (rq & 1); // even n (global)
    const size_t pb = ((size_t)rb * NS) * NF + rn;

    __syncthreads();

    float2 pr = make_float2(0.f, 0.f);
    if (tid < 256) pr = *(const float2*)&g_P[pb];

    for (int s = 0; s < NS; ++s) {
        if (s > 0) {
            if ((warp & 3) == 0) {
                const unsigned tgt = (unsigned)s << 3;   // 8 producers
                unsigned v;
                do {
                    asm volatile("ld.acquire.gpu.global.u32 %0, [%1];"
                                 : "=r"(v) : "l"(rdctr));
                } while (v < tgt);
            }
            asm volatile("bar.sync %0, 128;" :: "r"(Q + 1) : "memory");
        }

        ull* red = redb + (s & 1) * 4096;   // parity buffer

        const float* __restrict__ hq =
            g_ring + ((s + 1) & 1) * (1032 * 64) + B0 + 4 * bq;

        ull acc[4][2];
#pragma unroll
        for (int i = 0; i < 4; i++) { acc[i][0] = 0ull; acc[i][1] = 0ull; }

        float4 pf[8];
#pragma unroll
        for (int j = 0; j < 8; ++j)
            pf[j] = *(const float4*)(hq + (kbase + j) * 64);
#pragma unroll 8
        for (int kk = 0; kk < 64; ++kk) {
            const int slot = kk & 7;
            float4 h = pf[slot];
            pf[slot] = *(const float4*)(hq + (kbase + kk + 8) * 64);
            ulonglong2 w = *(const ulonglong2*)(wsm + (kbase + kk) * 32 + 4 * nq);
            ull h0d = pack2(h.x), h1d = pack2(h.y);
            ull h2d = pack2(h.z), h3d = pack2(h.w);
            fma2(acc[0][0], h0d, w.x); fma2(acc[0][1], h0d, w.y);
            fma2(acc[1][0], h1d, w.x); fma2(acc[1][1], h1d, w.y);
            fma2(acc[2][0], h2d, w.x); fma2(acc[2][1], h2d, w.y);
            fma2(acc[3][0], h3d, w.x); fma2(acc[3][1], h3d, w.y);
        }

#pragma unroll
        for (int i = 0; i < 4; i++)
#pragma unroll
            for (int p = 0; p < 2; p++)
                red[((warp * 8) + (i * 2 + p)) * 32 + lane] = acc[i][p];
        __syncthreads();                        // sync1: partials visible

        if (tid < 256) {
            float sx = 0.f, sy = 0.f;
#pragma unroll
            for (int w2 = 0; w2 < 16; ++w2) {
                float2 v = unpack2(red[(w2 * 8 + rq) * 32 + rl]);
                sx += v.x; sy += v.y;
            }
            float r0 = tanhf(sx + pr.x);
            float r1 = tanhf(sy + pr.y);
            float* rc = g_ring + (s & 1) * (1032 * 64);
            rc[rn * 64 + rb] = r0;
            rc[(rn + 1) * 64 + rb] = r1;

            if (s != NS - 1) {
                // Writers-only rendezvous; then publish.
                asm volatile("bar.sync 5, 256;" ::: "memory");
                if (tid == 0) {
                    asm volatile("red.release.gpu.global.add.u32 [%0], %1;"
                                 :: "l"(myctr), "r"(1u) : "memory");
                }
                *(float2*)&g_H[pb + (size_t)s * NF] =
                    make_float2(tf32r(r0), tf32r(r1));
                pr = *(const float2*)&g_P[pb + (size_t)(s + 1) * NF];
            } else {
                *(float2*)&g_H[pb + (size_t)s * NF] =
                    make_float2(tf32r(r0), tf32r(r1));
            }
        }
        // warps 8-15: no trailing barrier; straight to next quarter gate.
    }
}

extern "C" void kernel_launch(void* const* d_in, const int* in_sizes, int n_in,
                              void* d_out, int out_size)
{
    const float* x   = (const float*)d_in[0];
    const float* h0  = (const float*)d_in[1];
    const float* Wih = (const float*)d_in[2];
    const float* bih = (const float*)d_in[3];
    const float* Who = (const float*)d_in[4];
    const float* bho = (const float*)d_in[5];
    float* out = (float*)d_out;

    float *pP = nullptr, *pH = nullptr, *pWx = nullptr, *pWo = nullptr;
    cudaGetSymbolAddress((void**)&pP, g_P);
    cudaGetSymbolAddress((void**)&pH, g_H);
    cudaGetSymbolAddress((void**)&pWx, g_Wx);
    cudaGetSymbolAddress((void**)&pWo, g_Who);

    const int GEMM_SMEM = 3 * 2 * 128 * SST * 4;   // 110592 B
    const int SCAN_SMEM = 131072 + 65536;          // 196608 B

    static bool attr_done = false;
    if (!attr_done) {
        cudaFuncSetAttribute(rnn_scan, cudaFuncAttributeMaxDynamicSharedMemorySize, SCAN_SMEM);
        cudaFuncSetAttribute(gemm_mma, cudaFuncAttributeMaxDynamicSharedMemorySize, GEMM_SMEM);
        attr_done = true;
    }

    // user idx 0: fused init (weights + ring + counters)
    fused_init<<<4096, 256>>>(Wih, Who, h0);
    // user idx 1: x_proj = round(x) @ W_x^T + b_ih -> g_P (A rounded in-reg)
    gemm_mma<<<dim3(8, 256), 256, GEMM_SMEM>>>(x, pWx, bih, pP);
    // user idx 2: pad so profiler (user idx 3) hits the scan
    knop<<<1, 32>>>();
    // user idx 3: persistent recurrence scan  <-- ncu capture
    rnn_scan<<<128, 512, SCAN_SMEM>>>(Wih);
    // user idx 4: out = h @ W_ho^T + b_ho
    gemm_mma<<<dim3(8, 256), 256, GEMM_SMEM>>>(pH, pWo, bho, out);
}